// round 7
// baseline (speedup 1.0000x reference)
#include <cuda_runtime.h>
#include <cuda_bf16.h>

// SE block: B=32, H=W=56 (HW=3136), C=256, R=16
#define HW     3136
#define CCH    256
#define NB     32
#define NS     49              // hw chunks (units) per batch
#define CHUNK  64              // hw rows per unit
#define NUNIT  (NB * NS)       // 1568 units, u = b*49 + s (batch-major)
#define NBLK   784             // persistent blocks; 2 pools + 2 scales each

// Scratch (__device__ globals; zero-init at load; self-resetting each launch)
__device__ float g_partial[NUNIT * CCH];   // [u][c]
__device__ float g_gate[NB * CCH];
__device__ unsigned g_done[NB];            // pool units completed per batch
__device__ unsigned g_used[NB];            // scale units consumed per batch
__device__ volatile int g_ready[NB];       // gate-published flag

struct SM {
    float4 red[256];       // pool reduction
    float  s_s[CCH];       // squeezed means
    float  s_h[16];        // hidden layer
    float  s_w1[CCH * 16]; // staged w1
    int    flag;
};

__device__ __forceinline__ void do_pool(int u, int t, int c4, int ho,
                                        const float4* __restrict__ x4,
                                        const float* __restrict__ w1,
                                        const float* __restrict__ b1,
                                        const float* __restrict__ w2,
                                        const float* __restrict__ b2,
                                        SM* sm) {
    const int b = u / NS, s = u - b * NS;
    const size_t base = ((size_t)b * HW + (size_t)s * CHUNK + ho) * (CCH / 4) + c4;

    float4 acc = make_float4(0.f, 0.f, 0.f, 0.f);
#pragma unroll
    for (int k = 0; k < CHUNK; k += 4) {
        float4 v = x4[base + (size_t)k * (CCH / 4)];
        acc.x += v.x; acc.y += v.y; acc.z += v.z; acc.w += v.w;
    }
    sm->red[t] = acc;
    __syncthreads();
    if (t < 64) {
        float4 a = sm->red[t], e = sm->red[t + 64], f = sm->red[t + 128], h = sm->red[t + 192];
        float4 r = make_float4(a.x + e.x + f.x + h.x,
                               a.y + e.y + f.y + h.y,
                               a.z + e.z + f.z + h.z,
                               a.w + e.w + f.w + h.w);
        reinterpret_cast<float4*>(g_partial)[(size_t)u * (CCH / 4) + t] = r;
    }
    __threadfence();
    __syncthreads();
    if (t == 0) {
        unsigned old = atomicAdd(&g_done[b], 1u);
        sm->flag = (old == NS - 1);
    }
    __syncthreads();
    if (!sm->flag) return;

    // ---- last pool block of batch b: excitation MLP ----
#pragma unroll
    for (int i = t; i < CCH * 16; i += 256) sm->s_w1[i] = w1[i];

    float accm = 0.f;
#pragma unroll
    for (int ss = 0; ss < NS; ss++)
        accm += __ldcg(&g_partial[((size_t)b * NS + ss) * CCH + t]);
    sm->s_s[t] = accm * (1.0f / (float)HW);
    __syncthreads();

    if (t < 16) {
        float h = b1[t];
#pragma unroll 8
        for (int k = 0; k < CCH; k++)
            h = fmaf(sm->s_s[k], sm->s_w1[k * 16 + t], h);
        sm->s_h[t] = fmaxf(h, 0.f);
    }
    __syncthreads();

    float g = b2[t];
#pragma unroll
    for (int j = 0; j < 16; j++)
        g = fmaf(sm->s_h[j], w2[j * CCH + t], g);
    g_gate[b * CCH + t] = 1.f / (1.f + __expf(-g));

    __threadfence();
    __syncthreads();
    if (t == 0) g_ready[b] = 1;
    __syncthreads();
}

__device__ __forceinline__ void do_scale(int u, int t, int c4, int ho,
                                         const float4* __restrict__ x4,
                                         float4* __restrict__ o4) {
    const int b = u / NS, s = u - b * NS;

    if (t == 0) {
        while (g_ready[b] == 0) __nanosleep(32);
    }
    __syncthreads();

    const float* gp = g_gate + b * CCH + 4 * c4;
    float4 g;
    g.x = __ldcg(gp + 0); g.y = __ldcg(gp + 1);
    g.z = __ldcg(gp + 2); g.w = __ldcg(gp + 3);

    const size_t base = ((size_t)b * HW + (size_t)s * CHUNK + ho) * (CCH / 4) + c4;
#pragma unroll
    for (int k = 0; k < CHUNK; k += 4) {
        const size_t idx = base + (size_t)k * (CCH / 4);
        float4 v = __ldcs(&x4[idx]);   // last use of x: evict-first
        v.x *= g.x; v.y *= g.y; v.z *= g.z; v.w *= g.w;
        __stcs(&o4[idx], v);           // streaming store
    }

    __syncthreads();
    if (t == 0) {
        unsigned old = atomicAdd(&g_used[b], 1u);
        if (old == NS - 1) {           // last consumer: reset for next graph replay
            g_used[b]  = 0;
            g_done[b]  = 0;
            g_ready[b] = 0;
        }
    }
    __syncthreads();
}

__global__ void __launch_bounds__(256, 6)
k_se(const float* __restrict__ x,
     const float* __restrict__ w1,
     const float* __restrict__ b1,
     const float* __restrict__ w2,
     const float* __restrict__ b2,
     float* __restrict__ out) {
    const int i = blockIdx.x;
    const int t = threadIdx.x;
    const int c4 = t & 63;
    const int ho = t >> 6;

    const float4* x4 = reinterpret_cast<const float4*>(x);
    float4*       o4 = reinterpret_cast<float4*>(out);

    __shared__ SM sm;

    // Static balanced schedule: P(i), P(i+784), S(i), S(i+784)
    do_pool(i,          t, c4, ho, x4, w1, b1, w2, b2, &sm);
    do_pool(i + NBLK,   t, c4, ho, x4, w1, b1, w2, b2, &sm);
    do_scale(i,         t, c4, ho, x4, o4);
    do_scale(i + NBLK,  t, c4, ho, x4, o4);
}

extern "C" void kernel_launch(void* const* d_in, const int* in_sizes, int n_in,
                              void* d_out, int out_size) {
    const float* x  = (const float*)d_in[0];
    const float* w1 = (const float*)d_in[1];
    const float* b1 = (const float*)d_in[2];
    const float* w2 = (const float*)d_in[3];
    const float* b2 = (const float*)d_in[4];
    float* out = (float*)d_out;

    k_se<<<NBLK, 256>>>(x, w1, b1, w2, b2, out);
}